// round 3
// baseline (speedup 1.0000x reference)
#include <cuda_runtime.h>
#include <cuda_bf16.h>
#include <cstdint>

// Problem constants
static constexpr int BATCH = 8192;
static constexpr int SEQ   = 658;
static constexpr int INP   = 7;
static constexpr int D1    = 1024;
static constexpr int D2    = 512;
static constexpr int D3    = 128;

// Scratch (feature-major layouts: [feature][batch], batch contiguous)
__device__ float g_xw[(size_t)SEQ * BATCH];  // [t][b] : xw + b_ih + b_hh
__device__ float g_hs[(size_t)SEQ * BATCH];  // [t][b] : RNN hidden states
__device__ float g_a1[(size_t)D1 * BATCH];   // [d1][b]
__device__ float g_a2[(size_t)D2 * BATCH];   // [d2][b]
__device__ float g_a3[(size_t)D3 * BATCH];   // [d3][b]

// ---------------------------------------------------------------------------
// Kernel 1: input projection. xw[t][b] = dot(x[b,t,:], W_ih) + b_ih + b_hh
// Tile (32 b) x (32 t) through SMEM so x reads and xw writes are both coalesced.
// ---------------------------------------------------------------------------
__global__ __launch_bounds__(256)
void xw_kernel(const float* __restrict__ x,
               const float* __restrict__ W_ih,
               const float* __restrict__ b_ih,
               const float* __restrict__ b_hh,
               float* __restrict__ xw) {
    __shared__ float sx[32 * 225];  // 32 rows of 224 (=32*7) floats, +1 pad stride
    const int b0 = blockIdx.x * 32;
    const int t0 = blockIdx.y * 32;
    const int tid = threadIdx.x;

    // Load: per bb row, 224 contiguous floats of x
    for (int e = tid; e < 32 * 224; e += 256) {
        int bb = e / 224, rem = e % 224;
        int t = t0 + rem / 7;
        float v = 0.f;
        if (t < SEQ)
            v = x[((size_t)(b0 + bb) * SEQ + t0) * INP + rem];
        sx[bb * 225 + rem] = v;
    }
    __syncthreads();

    const float w0 = W_ih[0], w1 = W_ih[1], w2 = W_ih[2], w3 = W_ih[3];
    const float w4 = W_ih[4], w5 = W_ih[5], w6 = W_ih[6];
    const float bias = b_ih[0] + b_hh[0];

    for (int e = tid; e < 1024; e += 256) {
        int bb = e % 32, tt = e / 32;
        int t = t0 + tt;
        if (t < SEQ) {
            const float* p = &sx[bb * 225 + tt * 7];
            float s = bias;
            s = fmaf(p[0], w0, s); s = fmaf(p[1], w1, s);
            s = fmaf(p[2], w2, s); s = fmaf(p[3], w3, s);
            s = fmaf(p[4], w4, s); s = fmaf(p[5], w5, s);
            s = fmaf(p[6], w6, s);
            xw[(size_t)t * BATCH + (b0 + bb)] = s;  // coalesced over bb
        }
    }
}

// ---------------------------------------------------------------------------
// Kernel 2: RNN scan. One thread per batch lane. H=1 -> scalar recurrence.
// tanh(u) = 1 - 2/(exp(2u)+1), accurate & fast-math-independent.
// ---------------------------------------------------------------------------
__global__ __launch_bounds__(256)
void rnn_kernel(const float* __restrict__ xw,
                const float* __restrict__ h0,
                const float* __restrict__ W_hh,
                float* __restrict__ hs,
                float* __restrict__ hid_out,   // may be null
                int write_hidden) {
    int b = blockIdx.x * blockDim.x + threadIdx.x;
    if (b >= BATCH) return;
    float h = h0[b];
    const float w = W_hh[0];
    for (int t = 0; t < SEQ; t++) {
        float u = fmaf(w, h, xw[(size_t)t * BATCH + b]);
        float e = __expf(2.f * u);
        h = fmaf(-2.f, __fdividef(1.f, e + 1.f), 1.f);
        hs[(size_t)t * BATCH + b] = h;
    }
    if (write_hidden) hid_out[b] = h;
}

// ---------------------------------------------------------------------------
// Kernel 3: generic fp32 SGEMM. C[m][n] = sum_k A(m,k) * B(k,n) + bias, relu?
//   AT=false: A[m*K+k]   AT=true: A[k*M+m]
//   BT=false: B[k*N+n]   BT=true: B[n*K+k]
//   BIASN: bias indexed by n, else by m.
// 128x128 tile, BK=16, 256 threads, 8x8 register tile.
// ---------------------------------------------------------------------------
template <bool AT, bool BT, bool RELU, bool BIASN>
__global__ __launch_bounds__(256)
void gemm_kernel(const float* __restrict__ A, const float* __restrict__ B,
                 const float* __restrict__ bias, float* __restrict__ C,
                 int M, int N, int K) {
    constexpr int BM = 128, BN = 128, BK = 16;
    __shared__ float As[BK][BM + 4];
    __shared__ float Bs[BK][BN + 4];

    const int tid = threadIdx.x;
    const int m0 = blockIdx.y * BM;
    const int n0 = blockIdx.x * BN;
    const int tm = (tid / 16) * 8;
    const int tn = (tid % 16) * 8;

    float acc[8][8];
#pragma unroll
    for (int i = 0; i < 8; i++)
#pragma unroll
        for (int j = 0; j < 8; j++) acc[i][j] = 0.f;

    for (int k0 = 0; k0 < K; k0 += BK) {
        // Load A tile
        if (AT) {
#pragma unroll
            for (int i = 0; i < 8; i++) {
                int e = tid + i * 256;
                int kk = e / BM, mm = e % BM;
                int k = k0 + kk, m = m0 + mm;
                As[kk][mm] = (k < K && m < M) ? A[(size_t)k * M + m] : 0.f;
            }
        } else {
#pragma unroll
            for (int i = 0; i < 8; i++) {
                int e = tid + i * 256;
                int mm = e / BK, kk = e % BK;
                int k = k0 + kk, m = m0 + mm;
                As[kk][mm] = (k < K && m < M) ? A[(size_t)m * K + k] : 0.f;
            }
        }
        // Load B tile
        if (BT) {
#pragma unroll
            for (int i = 0; i < 8; i++) {
                int e = tid + i * 256;
                int nn = e / BK, kk = e % BK;
                int k = k0 + kk, n = n0 + nn;
                Bs[kk][nn] = (k < K && n < N) ? B[(size_t)n * K + k] : 0.f;
            }
        } else {
#pragma unroll
            for (int i = 0; i < 8; i++) {
                int e = tid + i * 256;
                int kk = e / BN, nn = e % BN;
                int k = k0 + kk, n = n0 + nn;
                Bs[kk][nn] = (k < K && n < N) ? B[(size_t)k * N + n] : 0.f;
            }
        }
        __syncthreads();

#pragma unroll
        for (int kk = 0; kk < BK; kk++) {
            float a[8], b[8];
#pragma unroll
            for (int i = 0; i < 8; i++) a[i] = As[kk][tm + i];
#pragma unroll
            for (int j = 0; j < 8; j++) b[j] = Bs[kk][tn + j];
#pragma unroll
            for (int i = 0; i < 8; i++)
#pragma unroll
                for (int j = 0; j < 8; j++) acc[i][j] = fmaf(a[i], b[j], acc[i][j]);
        }
        __syncthreads();
    }

#pragma unroll
    for (int i = 0; i < 8; i++) {
        int m = m0 + tm + i;
        if (m >= M) continue;
        float bm = BIASN ? 0.f : bias[m];
#pragma unroll
        for (int j = 0; j < 8; j++) {
            int n = n0 + tn + j;
            if (n >= N) continue;
            float v = acc[i][j] + (BIASN ? bias[n] : bm);
            if (RELU) v = fmaxf(v, 0.f);
            C[(size_t)m * N + n] = v;
        }
    }
}

// ---------------------------------------------------------------------------
// Launch
// ---------------------------------------------------------------------------
extern "C" void kernel_launch(void* const* d_in, const int* in_sizes, int n_in,
                              void* d_out, int out_size) {
    const float* x    = (const float*)d_in[0];
    const float* h0   = (const float*)d_in[1];
    const float* W_ih = (const float*)d_in[2];
    const float* W_hh = (const float*)d_in[3];
    const float* b_ih = (const float*)d_in[4];
    const float* b_hh = (const float*)d_in[5];
    const float* w1   = (const float*)d_in[6];
    const float* b1   = (const float*)d_in[7];
    const float* w2   = (const float*)d_in[8];
    const float* b2   = (const float*)d_in[9];
    const float* w3   = (const float*)d_in[10];
    const float* b3   = (const float*)d_in[11];
    const float* w4   = (const float*)d_in[12];
    const float* b4   = (const float*)d_in[13];
    float* out = (float*)d_out;

    float *p_xw, *p_hs, *p_a1, *p_a2, *p_a3;
    cudaGetSymbolAddress((void**)&p_xw, g_xw);
    cudaGetSymbolAddress((void**)&p_hs, g_hs);
    cudaGetSymbolAddress((void**)&p_a1, g_a1);
    cudaGetSymbolAddress((void**)&p_a2, g_a2);
    cudaGetSymbolAddress((void**)&p_a3, g_a3);

    const size_t out_elems = (size_t)BATCH * SEQ;
    const int write_hidden = ((size_t)out_size >= out_elems + BATCH) ? 1 : 0;
    float* hid_out = out + out_elems;

    // 1) input projection -> g_xw [t][b]
    {
        dim3 grid(BATCH / 32, (SEQ + 31) / 32);
        xw_kernel<<<grid, 256>>>(x, W_ih, b_ih, b_hh, p_xw);
    }
    // 2) RNN scan -> g_hs [t][b], final hidden -> d_out tail
    rnn_kernel<<<BATCH / 256, 256>>>(p_xw, h0, W_hh, p_hs, hid_out, write_hidden);

    // 3) MLP. Layers 1-3 compute C[d][b] (feature-major), layer 4 writes
    //    d_out[b][t] row-major directly.
    // L1: a1[d1][b] = relu(w1[d1][t] * hs[t][b] + b1[d1])  M=D1,N=B,K=T
    {
        dim3 grid(BATCH / 128, D1 / 128);
        gemm_kernel<false, false, true, false><<<grid, 256>>>(w1, p_hs, b1, p_a1, D1, BATCH, SEQ);
    }
    // L2: a2[d2][b] = relu(w2 * a1 + b2)  M=D2,N=B,K=D1
    {
        dim3 grid(BATCH / 128, D2 / 128);
        gemm_kernel<false, false, true, false><<<grid, 256>>>(w2, p_a1, b2, p_a2, D2, BATCH, D1);
    }
    // L3: a3[d3][b] = relu(w3 * a2 + b3)  M=D3,N=B,K=D2
    {
        dim3 grid(BATCH / 128, D3 / 128);
        gemm_kernel<false, false, true, false><<<grid, 256>>>(w3, p_a2, b3, p_a3, D3, BATCH, D2);
    }
    // L4: out[b][t] = a3[k][b]^T * w4[t][k]^T + b4[t]  M=B,N=T,K=D3
    //     A transposed (A[k*M+m]), B transposed (B[n*K+k]), bias on n, no relu.
    {
        dim3 grid((SEQ + 127) / 128, BATCH / 128);
        gemm_kernel<true, true, false, true><<<grid, 256>>>(p_a3, w4, b4, out, BATCH, SEQ, D3);
    }
}

// round 8
// speedup vs baseline: 1.4245x; 1.4245x over previous
#include <cuda_runtime.h>
#include <cuda_bf16.h>
#include <cstdint>

// R7: identical resubmit of R5/R6 HMMA kernel to disambiguate broker flake
// from deterministic failure. Full audit found no hang/crash path.

static constexpr int BATCH = 8192;
static constexpr int SEQ   = 658;
static constexpr int INP   = 7;
static constexpr int D1    = 1024;
static constexpr int D2    = 512;
static constexpr int D3    = 128;
static constexpr int KP_T  = 704;   // SEQ padded to multiple of 32
static constexpr int M4P   = 768;   // L4 M (=SEQ) padded to multiple of 128

// ---------------- device scratch ----------------
__device__ __align__(16) float g_xw[(size_t)SEQ * BATCH];   // [t][b]
__device__ __align__(16) float g_hs[(size_t)SEQ * BATCH];   // [t][b]
// bf16 split activations, batch-major [b][k]
__device__ __align__(16) __nv_bfloat16 g_hsT_hi[(size_t)BATCH * KP_T];
__device__ __align__(16) __nv_bfloat16 g_hsT_lo[(size_t)BATCH * KP_T];
__device__ __align__(16) __nv_bfloat16 g_a1_hi[(size_t)BATCH * D1];
__device__ __align__(16) __nv_bfloat16 g_a1_lo[(size_t)BATCH * D1];
__device__ __align__(16) __nv_bfloat16 g_a2_hi[(size_t)BATCH * D2];
__device__ __align__(16) __nv_bfloat16 g_a2_lo[(size_t)BATCH * D2];
__device__ __align__(16) __nv_bfloat16 g_a3_hi[(size_t)BATCH * D3];
__device__ __align__(16) __nv_bfloat16 g_a3_lo[(size_t)BATCH * D3];
// bf16 split weights, K-major [m][k], zero-padded
__device__ __align__(16) __nv_bfloat16 g_w1_hi[(size_t)D1 * KP_T];
__device__ __align__(16) __nv_bfloat16 g_w1_lo[(size_t)D1 * KP_T];
__device__ __align__(16) __nv_bfloat16 g_w2_hi[(size_t)D2 * D1];
__device__ __align__(16) __nv_bfloat16 g_w2_lo[(size_t)D2 * D1];
__device__ __align__(16) __nv_bfloat16 g_w3_hi[(size_t)D3 * D2];
__device__ __align__(16) __nv_bfloat16 g_w3_lo[(size_t)D3 * D2];
__device__ __align__(16) __nv_bfloat16 g_w4_hi[(size_t)M4P * D3];
__device__ __align__(16) __nv_bfloat16 g_w4_lo[(size_t)M4P * D3];

// ---------------- helpers ----------------
__device__ __forceinline__ uint32_t smem_u32(const void* p) {
    uint32_t a;
    asm("{ .reg .u64 t; cvta.to.shared.u64 t, %1; cvt.u32.u64 %0, t; }" : "=r"(a) : "l"(p));
    return a;
}
#define CP_ASYNC16(s, g) \
    asm volatile("cp.async.cg.shared.global [%0], [%1], 16;" :: "r"(s), "l"(g) : "memory")
#define CP_COMMIT() asm volatile("cp.async.commit_group;" ::: "memory")
#define CP_WAIT0()  asm volatile("cp.async.wait_group 0;" ::: "memory")

#define LDSM4(R0, R1, R2, R3, ADDR) \
    asm volatile("ldmatrix.sync.aligned.m8n8.x4.shared.b16 {%0,%1,%2,%3}, [%4];" \
                 : "=r"(R0), "=r"(R1), "=r"(R2), "=r"(R3) : "r"(ADDR))

#define MMA_BF16(D, A, B0, B1) \
    asm volatile("mma.sync.aligned.m16n8k16.row.col.f32.bf16.bf16.f32 " \
                 "{%0,%1,%2,%3}, {%4,%5,%6,%7}, {%8,%9}, {%0,%1,%2,%3};" \
                 : "+f"((D)[0]), "+f"((D)[1]), "+f"((D)[2]), "+f"((D)[3]) \
                 : "r"((A)[0]), "r"((A)[1]), "r"((A)[2]), "r"((A)[3]), \
                   "r"(B0), "r"(B1))

__device__ __forceinline__ void store_split(__nv_bfloat16* __restrict__ hi,
                                            __nv_bfloat16* __restrict__ lo,
                                            size_t idx, float v) {
    __nv_bfloat16 h = __float2bfloat16(v);
    hi[idx] = h;
    lo[idx] = __float2bfloat16(v - __bfloat162float(h));
}

// ---------------------------------------------------------------------------
// Kernel 1: input projection. xw[t][b] = dot(x[b,t,:], W_ih) + b_ih + b_hh
// ---------------------------------------------------------------------------
__global__ __launch_bounds__(256)
void xw_kernel(const float* __restrict__ x,
               const float* __restrict__ W_ih,
               const float* __restrict__ b_ih,
               const float* __restrict__ b_hh,
               float* __restrict__ xw) {
    __shared__ float sx[32 * 225];
    const int b0 = blockIdx.x * 32;
    const int t0 = blockIdx.y * 32;
    const int tid = threadIdx.x;

    for (int e = tid; e < 32 * 224; e += 256) {
        int bb = e / 224, rem = e % 224;
        int t = t0 + rem / 7;
        float v = 0.f;
        if (t < SEQ)
            v = x[((size_t)(b0 + bb) * SEQ + t0) * INP + rem];
        sx[bb * 225 + rem] = v;
    }
    __syncthreads();

    const float w0 = W_ih[0], w1 = W_ih[1], w2 = W_ih[2], w3 = W_ih[3];
    const float w4 = W_ih[4], w5 = W_ih[5], w6 = W_ih[6];
    const float bias = b_ih[0] + b_hh[0];

    for (int e = tid; e < 1024; e += 256) {
        int bb = e % 32, tt = e / 32;
        int t = t0 + tt;
        if (t < SEQ) {
            const float* p = &sx[bb * 225 + tt * 7];
            float s = bias;
            s = fmaf(p[0], w0, s); s = fmaf(p[1], w1, s);
            s = fmaf(p[2], w2, s); s = fmaf(p[3], w3, s);
            s = fmaf(p[4], w4, s); s = fmaf(p[5], w5, s);
            s = fmaf(p[6], w6, s);
            xw[(size_t)t * BATCH + (b0 + bb)] = s;
        }
    }
}

// ---------------------------------------------------------------------------
// Kernel 2: RNN scan (H=1 scalar recurrence)
// ---------------------------------------------------------------------------
__global__ __launch_bounds__(128)
void rnn_kernel(const float* __restrict__ xw,
                const float* __restrict__ h0,
                const float* __restrict__ W_hh,
                float* __restrict__ hs,
                float* __restrict__ hid_out,
                int write_hidden) {
    int b = blockIdx.x * blockDim.x + threadIdx.x;
    if (b >= BATCH) return;
    float h = h0[b];
    const float w = W_hh[0];
    for (int t = 0; t < SEQ; t++) {
        float u = fmaf(w, h, xw[(size_t)t * BATCH + b]);
        float e = __expf(2.f * u);
        h = fmaf(-2.f, __fdividef(1.f, e + 1.f), 1.f);
        hs[(size_t)t * BATCH + b] = h;
    }
    if (write_hidden) hid_out[b] = h;
}

// ---------------------------------------------------------------------------
// Kernel 3: transpose hs [t][b] -> batch-major bf16 split [b][KP_T] (pad = 0)
// ---------------------------------------------------------------------------
__global__ __launch_bounds__(256)
void transpose_split_kernel(const float* __restrict__ hs,
                            __nv_bfloat16* __restrict__ hi,
                            __nv_bfloat16* __restrict__ lo) {
    __shared__ float tile[32][33];
    const int b0 = blockIdx.x * 32, t0 = blockIdx.y * 32;
    const int lx = threadIdx.x & 31, ly = threadIdx.x >> 5;  // ly 0..7
#pragma unroll
    for (int r = 0; r < 4; r++) {
        int t = t0 + ly + r * 8;
        tile[ly + r * 8][lx] = (t < SEQ) ? hs[(size_t)t * BATCH + b0 + lx] : 0.f;
    }
    __syncthreads();
#pragma unroll
    for (int r = 0; r < 4; r++) {
        int b = b0 + ly + r * 8;
        float v = tile[lx][ly + r * 8];
        store_split(hi, lo, (size_t)b * KP_T + t0 + lx, v);
    }
}

// ---------------------------------------------------------------------------
// Kernel 4: fp32 -> padded bf16 hi/lo split (weights)
// ---------------------------------------------------------------------------
__global__ __launch_bounds__(256)
void split_pad_kernel(const float* __restrict__ src, int Mv, int Kv, int Mp, int Kp,
                      __nv_bfloat16* __restrict__ hi, __nv_bfloat16* __restrict__ lo) {
    size_t total = (size_t)Mp * Kp;
    for (size_t i = (size_t)blockIdx.x * blockDim.x + threadIdx.x; i < total;
         i += (size_t)gridDim.x * blockDim.x) {
        int r = (int)(i / Kp), c = (int)(i % Kp);
        float v = (r < Mv && c < Kv) ? src[(size_t)r * Kv + c] : 0.f;
        store_split(hi, lo, i, v);
    }
}

// ---------------------------------------------------------------------------
// Kernel 5: HMMA (mma.sync m16n8k16 bf16) GEMM, split-bf16 3-pass.
//   C[m][n] = sum_k A[m][k]*B[n][k] + bias[m]
//   CTA tile 128(m) x 128(n), BK=32, 256 threads, warp tile 32x64.
//   SMEM row stride 40 elems (80B) -> conflict-free ldmatrix.
//   cp.async double-buffered pipeline.
// ---------------------------------------------------------------------------
static constexpr uint32_t T_AH = 0, T_AL = 10240, T_BH = 20480, T_BL = 30720;
static constexpr uint32_t STAGE_B = 40960;
static constexpr int SMEM_DYN = 2 * STAGE_B;  // 80 KB

template <bool RELU, bool SPLIT_OUT>
__global__ __launch_bounds__(256, 1)
void mma_gemm_kernel(const __nv_bfloat16* __restrict__ Ahi, const __nv_bfloat16* __restrict__ Alo,
                     const __nv_bfloat16* __restrict__ Bhi, const __nv_bfloat16* __restrict__ Blo,
                     const float* __restrict__ bias,
                     __nv_bfloat16* __restrict__ Chi, __nv_bfloat16* __restrict__ Clo,
                     float* __restrict__ Cf,
                     int Kpad, int Dout, int Mvalid) {
    extern __shared__ __align__(16) char smem[];
    const int tid  = threadIdx.x;
    const int lane = tid & 31;
    const int wid  = tid >> 5;
    const int m0 = blockIdx.y * 128;
    const int n0 = blockIdx.x * 128;
    const int m_base = (wid & 3) * 32;   // 4 warps over m
    const int n_base = (wid >> 2) * 64;  // 2 warps over n
    const uint32_t sbase = smem_u32(smem);

    const __nv_bfloat16* gAh = Ahi + (size_t)m0 * Kpad;
    const __nv_bfloat16* gAl = Alo + (size_t)m0 * Kpad;
    const __nv_bfloat16* gBh = Bhi + (size_t)n0 * Kpad;
    const __nv_bfloat16* gBl = Blo + (size_t)n0 * Kpad;

    float acc[2][8][4];
#pragma unroll
    for (int mi = 0; mi < 2; mi++)
#pragma unroll
        for (int ni = 0; ni < 8; ni++)
#pragma unroll
            for (int v = 0; v < 4; v++) acc[mi][ni][v] = 0.f;

    const int stages = Kpad >> 5;

    auto load_stage = [&](int s, int buf) {
        const uint32_t sb = sbase + buf * STAGE_B;
        const int kofs = s << 5;  // elements
#pragma unroll
        for (int i = 0; i < 2; i++) {
            const int ci = tid + i * 256;       // 0..511
            const int rr = ci >> 2, cc = ci & 3;
            const uint32_t so = rr * 80 + cc * 16;
            const size_t go = (size_t)rr * Kpad + kofs + cc * 8;
            CP_ASYNC16(sb + T_AH + so, gAh + go);
            CP_ASYNC16(sb + T_AL + so, gAl + go);
            CP_ASYNC16(sb + T_BH + so, gBh + go);
            CP_ASYNC16(sb + T_BL + so, gBl + go);
        }
    };

    load_stage(0, 0);
    CP_COMMIT();

    for (int s = 0; s < stages; s++) {
        CP_WAIT0();
        __syncthreads();
        if (s + 1 < stages) { load_stage(s + 1, (s + 1) & 1); CP_COMMIT(); }
        const uint32_t sb = sbase + (s & 1) * STAGE_B;

#pragma unroll
        for (int step = 0; step < 2; step++) {
            const uint32_t kb = step * 32;  // byte offset within row (16 elems)
            uint32_t ah[2][4], al[2][4], b[8][2];
            const uint32_t arow = (uint32_t)(m_base + (lane & 15)) * 80 + kb + (lane >> 4) * 16;
#pragma unroll
            for (int mi = 0; mi < 2; mi++) {
                const uint32_t ad = sb + arow + mi * (16 * 80);
                LDSM4(ah[mi][0], ah[mi][1], ah[mi][2], ah[mi][3], ad + T_AH);
                LDSM4(al[mi][0], al[mi][1], al[mi][2], al[mi][3], ad + T_AL);
            }
            const uint32_t brow = (uint32_t)(n_base + (lane & 15)) * 80 + kb + (lane >> 4) * 16;
#pragma unroll
            for (int g = 0; g < 4; g++) {
                uint32_t t0, t1, t2, t3;
                LDSM4(t0, t1, t2, t3, sb + T_BH + brow + g * (16 * 80));
                b[2 * g][0] = t0; b[2 * g][1] = t2;
                b[2 * g + 1][0] = t1; b[2 * g + 1][1] = t3;
            }
            // pass 1: A_hi * B_hi
#pragma unroll
            for (int mi = 0; mi < 2; mi++)
#pragma unroll
                for (int ni = 0; ni < 8; ni++)
                    MMA_BF16(acc[mi][ni], ah[mi], b[ni][0], b[ni][1]);
            // pass 2: A_lo * B_hi
#pragma unroll
            for (int mi = 0; mi < 2; mi++)
#pragma unroll
                for (int ni = 0; ni < 8; ni++)
                    MMA_BF16(acc[mi][ni], al[mi], b[ni][0], b[ni][1]);
            // reload B as B_lo
#pragma unroll
            for (int g = 0; g < 4; g++) {
                uint32_t t0, t1, t2, t3;
                LDSM4(t0, t1, t2, t3, sb + T_BL + brow + g * (16 * 80));
                b[2 * g][0] = t0; b[2 * g][1] = t2;
                b[2 * g + 1][0] = t1; b[2 * g + 1][1] = t3;
            }
            // pass 3: A_hi * B_lo
#pragma unroll
            for (int mi = 0; mi < 2; mi++)
#pragma unroll
                for (int ni = 0; ni < 8; ni++)
                    MMA_BF16(acc[mi][ni], ah[mi], b[ni][0], b[ni][1]);
        }
    }

    // epilogue
    const int erow = lane >> 2;
    const int ecol = (lane & 3) * 2;
#pragma unroll
    for (int mi = 0; mi < 2; mi++) {
        const int mA = m0 + m_base + mi * 16 + erow;
        const int mB = mA + 8;
        const bool vA = mA < Mvalid, vB = mB < Mvalid;
        const float bA = vA ? bias[mA] : 0.f;
        const float bB = vB ? bias[mB] : 0.f;
#pragma unroll
        for (int ni = 0; ni < 8; ni++) {
            const int n = n0 + n_base + ni * 8 + ecol;
            float v00 = acc[mi][ni][0] + bA;
            float v01 = acc[mi][ni][1] + bA;
            float v10 = acc[mi][ni][2] + bB;
            float v11 = acc[mi][ni][3] + bB;
            if (RELU) {
                v00 = fmaxf(v00, 0.f); v01 = fmaxf(v01, 0.f);
                v10 = fmaxf(v10, 0.f); v11 = fmaxf(v11, 0.f);
            }
            if constexpr (SPLIT_OUT) {
                if (vA) {
                    store_split(Chi, Clo, (size_t)n * Dout + mA, v00);
                    store_split(Chi, Clo, (size_t)(n + 1) * Dout + mA, v01);
                }
                if (vB) {
                    store_split(Chi, Clo, (size_t)n * Dout + mB, v10);
                    store_split(Chi, Clo, (size_t)(n + 1) * Dout + mB, v11);
                }
            } else {
                if (vA) {
                    Cf[(size_t)n * Dout + mA] = v00;
                    Cf[(size_t)(n + 1) * Dout + mA] = v01;
                }
                if (vB) {
                    Cf[(size_t)n * Dout + mB] = v10;
                    Cf[(size_t)(n + 1) * Dout + mB] = v11;
                }
            }
        }
    }
}

// ---------------------------------------------------------------------------
// Launch
// ---------------------------------------------------------------------------
extern "C" void kernel_launch(void* const* d_in, const int* in_sizes, int n_in,
                              void* d_out, int out_size) {
    const float* x    = (const float*)d_in[0];
    const float* h0   = (const float*)d_in[1];
    const float* W_ih = (const float*)d_in[2];
    const float* W_hh = (const float*)d_in[3];
    const float* b_ih = (const float*)d_in[4];
    const float* b_hh = (const float*)d_in[5];
    const float* w1   = (const float*)d_in[6];
    const float* b1   = (const float*)d_in[7];
    const float* w2   = (const float*)d_in[8];
    const float* b2   = (const float*)d_in[9];
    const float* w3   = (const float*)d_in[10];
    const float* b3   = (const float*)d_in[11];
    const float* w4   = (const float*)d_in[12];
    const float* b4   = (const float*)d_in[13];
    float* out = (float*)d_out;

    float *p_xw, *p_hs;
    __nv_bfloat16 *hsT_hi, *hsT_lo, *a1h, *a1l, *a2h, *a2l, *a3h, *a3l;
    __nv_bfloat16 *w1h, *w1l, *w2h, *w2l, *w3h, *w3l, *w4h, *w4l;
    cudaGetSymbolAddress((void**)&p_xw, g_xw);
    cudaGetSymbolAddress((void**)&p_hs, g_hs);
    cudaGetSymbolAddress((void**)&hsT_hi, g_hsT_hi);
    cudaGetSymbolAddress((void**)&hsT_lo, g_hsT_lo);
    cudaGetSymbolAddress((void**)&a1h, g_a1_hi);
    cudaGetSymbolAddress((void**)&a1l, g_a1_lo);
    cudaGetSymbolAddress((void**)&a2h, g_a2_hi);
    cudaGetSymbolAddress((void**)&a2l, g_a2_lo);
    cudaGetSymbolAddress((void**)&a3h, g_a3_hi);
    cudaGetSymbolAddress((void**)&a3l, g_a3_lo);
    cudaGetSymbolAddress((void**)&w1h, g_w1_hi);
    cudaGetSymbolAddress((void**)&w1l, g_w1_lo);
    cudaGetSymbolAddress((void**)&w2h, g_w2_hi);
    cudaGetSymbolAddress((void**)&w2l, g_w2_lo);
    cudaGetSymbolAddress((void**)&w3h, g_w3_hi);
    cudaGetSymbolAddress((void**)&w3l, g_w3_lo);
    cudaGetSymbolAddress((void**)&w4h, g_w4_hi);
    cudaGetSymbolAddress((void**)&w4l, g_w4_lo);

    cudaFuncSetAttribute(mma_gemm_kernel<true, true>,
                         cudaFuncAttributeMaxDynamicSharedMemorySize, SMEM_DYN);
    cudaFuncSetAttribute(mma_gemm_kernel<false, false>,
                         cudaFuncAttributeMaxDynamicSharedMemorySize, SMEM_DYN);

    const size_t out_elems = (size_t)BATCH * SEQ;
    const int write_hidden = ((size_t)out_size >= out_elems + BATCH) ? 1 : 0;
    float* hid_out = out + out_elems;

    // Weight conversion (small)
    split_pad_kernel<<<704, 256>>>(w1, D1, SEQ, D1, KP_T, w1h, w1l);
    split_pad_kernel<<<512, 256>>>(w2, D2, D1, D2, D1, w2h, w2l);
    split_pad_kernel<<<256, 256>>>(w3, D3, D2, D3, D2, w3h, w3l);
    split_pad_kernel<<<96,  256>>>(w4, SEQ, D3, M4P, D3, w4h, w4l);

    // Input projection -> g_xw [t][b]
    {
        dim3 grid(BATCH / 32, (SEQ + 31) / 32);
        xw_kernel<<<grid, 256>>>(x, W_ih, b_ih, b_hh, p_xw);
    }
    // RNN scan -> g_hs [t][b], hidden tail
    rnn_kernel<<<BATCH / 128, 128>>>(p_xw, h0, W_hh, p_hs, hid_out, write_hidden);

    // Transpose + split -> hsT_hi/lo [b][KP_T]
    {
        dim3 grid(BATCH / 32, KP_T / 32);
        transpose_split_kernel<<<grid, 256>>>(p_hs, hsT_hi, hsT_lo);
    }

    // L1: a1[b][D1] = relu(w1 . hs + b1)
    {
        dim3 grid(BATCH / 128, D1 / 128);
        mma_gemm_kernel<true, true><<<grid, 256, SMEM_DYN>>>(
            w1h, w1l, hsT_hi, hsT_lo, b1, a1h, a1l, nullptr, KP_T, D1, D1);
    }
    // L2: a2[b][D2] = relu(w2 . a1 + b2)
    {
        dim3 grid(BATCH / 128, D2 / 128);
        mma_gemm_kernel<true, true><<<grid, 256, SMEM_DYN>>>(
            w2h, w2l, a1h, a1l, b2, a2h, a2l, nullptr, D1, D2, D2);
    }
    // L3: a3[b][D3] = relu(w3 . a2 + b3)
    {
        dim3 grid(BATCH / 128, D3 / 128);
        mma_gemm_kernel<true, true><<<grid, 256, SMEM_DYN>>>(
            w3h, w3l, a2h, a2l, b3, a3h, a3l, nullptr, D2, D3, D3);
    }
    // L4: out[b][t] = w4 . a3 + b4  (fp32 out, m = t, guard m < SEQ)
    {
        dim3 grid(BATCH / 128, M4P / 128);
        mma_gemm_kernel<false, false><<<grid, 256, SMEM_DYN>>>(
            w4h, w4l, a3h, a3l, b4, nullptr, nullptr, out, D3, SEQ, SEQ);
    }
}

// round 11
// speedup vs baseline: 2.7920x; 1.9601x over previous
#include <cuda_runtime.h>
#include <cuda_fp16.h>
#include <cstdint>

static constexpr int BATCH = 8192;
static constexpr int SEQ   = 658;
static constexpr int INP   = 7;
static constexpr int D1    = 1024;
static constexpr int D2    = 512;
static constexpr int D3    = 128;
static constexpr int KP_T  = 704;   // SEQ padded to multiple of 64
static constexpr int M4P   = 768;   // L4 M (=SEQ) padded to multiple of 128

// ---------------- device scratch ----------------
__device__ __align__(16) float  g_xw[(size_t)SEQ * BATCH];    // [t][b]
__device__ __align__(16) __half g_hs_h[(size_t)SEQ * BATCH];  // [t][b] fp16
// fp16 activations, batch-major [b][k]
__device__ __align__(16) __half g_hsT[(size_t)BATCH * KP_T];
__device__ __align__(16) __half g_a1[(size_t)BATCH * D1];
__device__ __align__(16) __half g_a2[(size_t)BATCH * D2];
__device__ __align__(16) __half g_a3[(size_t)BATCH * D3];
// fp16 split weights, K-major [m][k], zero-padded
__device__ __align__(16) __half g_w1_hi[(size_t)D1 * KP_T];
__device__ __align__(16) __half g_w1_lo[(size_t)D1 * KP_T];
__device__ __align__(16) __half g_w2_hi[(size_t)D2 * D1];
__device__ __align__(16) __half g_w2_lo[(size_t)D2 * D1];
__device__ __align__(16) __half g_w3_hi[(size_t)D3 * D2];
__device__ __align__(16) __half g_w3_lo[(size_t)D3 * D2];
__device__ __align__(16) __half g_w4_hi[(size_t)M4P * D3];
__device__ __align__(16) __half g_w4_lo[(size_t)M4P * D3];

// ---------------- helpers ----------------
__device__ __forceinline__ uint32_t smem_u32(const void* p) {
    uint32_t a;
    asm("{ .reg .u64 t; cvta.to.shared.u64 t, %1; cvt.u32.u64 %0, t; }" : "=r"(a) : "l"(p));
    return a;
}
#define CP_ASYNC16(s, g) \
    asm volatile("cp.async.cg.shared.global [%0], [%1], 16;" :: "r"(s), "l"(g) : "memory")
#define CP_COMMIT() asm volatile("cp.async.commit_group;" ::: "memory")
#define CP_WAIT0()  asm volatile("cp.async.wait_group 0;" ::: "memory")

#define LDSM4(R0, R1, R2, R3, ADDR) \
    asm volatile("ldmatrix.sync.aligned.m8n8.x4.shared.b16 {%0,%1,%2,%3}, [%4];" \
                 : "=r"(R0), "=r"(R1), "=r"(R2), "=r"(R3) : "r"(ADDR))

#define MMA_F16(D, A, B0, B1) \
    asm volatile("mma.sync.aligned.m16n8k16.row.col.f32.f16.f16.f32 " \
                 "{%0,%1,%2,%3}, {%4,%5,%6,%7}, {%8,%9}, {%0,%1,%2,%3};" \
                 : "+f"((D)[0]), "+f"((D)[1]), "+f"((D)[2]), "+f"((D)[3]) \
                 : "r"((A)[0]), "r"((A)[1]), "r"((A)[2]), "r"((A)[3]), \
                   "r"(B0), "r"(B1))

// ---------------------------------------------------------------------------
// Kernel 1: input projection. xw[t][b] = dot(x[b,t,:], W_ih) + b_ih + b_hh
// ---------------------------------------------------------------------------
__global__ __launch_bounds__(256)
void xw_kernel(const float* __restrict__ x,
               const float* __restrict__ W_ih,
               const float* __restrict__ b_ih,
               const float* __restrict__ b_hh,
               float* __restrict__ xw) {
    __shared__ float sx[32 * 225];
    const int b0 = blockIdx.x * 32;
    const int t0 = blockIdx.y * 32;
    const int tid = threadIdx.x;

    for (int e = tid; e < 32 * 224; e += 256) {
        int bb = e / 224, rem = e % 224;
        int t = t0 + rem / 7;
        float v = 0.f;
        if (t < SEQ)
            v = x[((size_t)(b0 + bb) * SEQ + t0) * INP + rem];
        sx[bb * 225 + rem] = v;
    }
    __syncthreads();

    const float w0 = W_ih[0], w1 = W_ih[1], w2 = W_ih[2], w3 = W_ih[3];
    const float w4 = W_ih[4], w5 = W_ih[5], w6 = W_ih[6];
    const float bias = b_ih[0] + b_hh[0];

    for (int e = tid; e < 1024; e += 256) {
        int bb = e % 32, tt = e / 32;
        int t = t0 + tt;
        if (t < SEQ) {
            const float* p = &sx[bb * 225 + tt * 7];
            float s = bias;
            s = fmaf(p[0], w0, s); s = fmaf(p[1], w1, s);
            s = fmaf(p[2], w2, s); s = fmaf(p[3], w3, s);
            s = fmaf(p[4], w4, s); s = fmaf(p[5], w5, s);
            s = fmaf(p[6], w6, s);
            xw[(size_t)t * BATCH + (b0 + bb)] = s;
        }
    }
}

// ---------------------------------------------------------------------------
// Kernel 2: RNN scan (H=1 scalar recurrence), writes fp16 hs
// ---------------------------------------------------------------------------
__global__ __launch_bounds__(128)
void rnn_kernel(const float* __restrict__ xw,
                const float* __restrict__ h0,
                const float* __restrict__ W_hh,
                __half* __restrict__ hs,
                float* __restrict__ hid_out,
                int write_hidden) {
    int b = blockIdx.x * blockDim.x + threadIdx.x;
    if (b >= BATCH) return;
    float h = h0[b];
    const float w = W_hh[0];
    for (int t = 0; t < SEQ; t++) {
        float u = fmaf(w, h, xw[(size_t)t * BATCH + b]);
        float e = __expf(2.f * u);
        h = fmaf(-2.f, __fdividef(1.f, e + 1.f), 1.f);
        hs[(size_t)t * BATCH + b] = __float2half(h);
    }
    if (write_hidden) hid_out[b] = h;
}

// ---------------------------------------------------------------------------
// Kernel 3: transpose hs [t][b] (fp16) -> [b][KP_T] (fp16, zero-padded)
// Consistent 64t x 64b tile through s[64 b][65 t-padded].
// ---------------------------------------------------------------------------
__global__ __launch_bounds__(256)
void transpose_kernel(const __half* __restrict__ hs, __half* __restrict__ hsT) {
    __shared__ __half s[64][65];   // [b][t]
    const int b0 = blockIdx.x * 64, t0 = blockIdx.y * 64;
    const int lx = threadIdx.x & 31, ly = threadIdx.x >> 5;  // ly 0..7
#pragma unroll
    for (int r = 0; r < 8; r++) {
        const int tt = ly + r * 8;          // 0..63
        const int t = t0 + tt;
        __half2 v = __float2half2_rn(0.f);
        if (t < SEQ)
            v = *reinterpret_cast<const __half2*>(hs + (size_t)t * BATCH + b0 + 2 * lx);
        s[2 * lx][tt]     = __low2half(v);
        s[2 * lx + 1][tt] = __high2half(v);
    }
    __syncthreads();
#pragma unroll
    for (int r = 0; r < 8; r++) {
        const int brow = ly + r * 8;        // 0..63
        __half2 v = __halves2half2(s[brow][2 * lx], s[brow][2 * lx + 1]);
        *reinterpret_cast<__half2*>(hsT + (size_t)(b0 + brow) * KP_T + t0 + 2 * lx) = v;
    }
}

// ---------------------------------------------------------------------------
// Kernel 4: all weight splits in ONE launch. 4096 elems per block.
// ---------------------------------------------------------------------------
__device__ __forceinline__ void split_seg(const float* __restrict__ src,
                                          int Mv, int Kv, int Kp,
                                          __half* __restrict__ hi,
                                          __half* __restrict__ lo, int blk) {
    const int base = blk * 4096;
#pragma unroll
    for (int i = 0; i < 16; i++) {
        int idx = base + threadIdx.x + i * 256;
        int r = idx / Kp, c = idx % Kp;
        float v = (r < Mv && c < Kv) ? src[(size_t)r * Kv + c] : 0.f;
        __half h = __float2half(v);
        hi[idx] = h;
        lo[idx] = __float2half(v - __half2float(h));
    }
}

static constexpr int SPLIT_B1 = (D1 * KP_T) / 4096;  // 176
static constexpr int SPLIT_B2 = (D2 * D1) / 4096;    // 128
static constexpr int SPLIT_B3 = (D3 * D2) / 4096;    // 16
static constexpr int SPLIT_B4 = (M4P * D3) / 4096;   // 24
static constexpr int SPLIT_BLOCKS = SPLIT_B1 + SPLIT_B2 + SPLIT_B3 + SPLIT_B4;

__global__ __launch_bounds__(256)
void weight_split_kernel(const float* __restrict__ w1, const float* __restrict__ w2,
                         const float* __restrict__ w3, const float* __restrict__ w4,
                         __half* w1h, __half* w1l, __half* w2h, __half* w2l,
                         __half* w3h, __half* w3l, __half* w4h, __half* w4l) {
    int blk = blockIdx.x;
    if (blk < SPLIT_B1) { split_seg(w1, D1, SEQ, KP_T, w1h, w1l, blk); return; }
    blk -= SPLIT_B1;
    if (blk < SPLIT_B2) { split_seg(w2, D2, D1, D1, w2h, w2l, blk); return; }
    blk -= SPLIT_B2;
    if (blk < SPLIT_B3) { split_seg(w3, D3, D2, D2, w3h, w3l, blk); return; }
    blk -= SPLIT_B3;
    split_seg(w4, SEQ, D3, D3, w4h, w4l, blk);
}

// ---------------------------------------------------------------------------
// Kernel 5: HMMA fp16 GEMM, weights split hi/lo (2 passes), activations fp16.
//   C[m][n] = sum_k (Ahi+Alo)[m][k] * B[n][k] + bias[m]
//   BM = WM*32, BN = 128 always. 256 threads, warp tile 32m x (NI*8)n.
//   SMEM row stride 40 halves (80B), cp.async double-buffered.
// ---------------------------------------------------------------------------
template <int WM, int NI, bool RELU, bool HALF_OUT>
__global__ __launch_bounds__(256)
void mma_gemm_kernel(const __half* __restrict__ Ahi, const __half* __restrict__ Alo,
                     const __half* __restrict__ B,
                     const float* __restrict__ bias,
                     __half* __restrict__ Ch, float* __restrict__ Cf,
                     int Kpad, int Dout, int Mvalid) {
    constexpr int BM = WM * 32;
    constexpr int WN = 8 / WM;
    static_assert(WN * NI * 8 == 128, "BN must be 128");
    constexpr uint32_t T_AL  = BM * 80;
    constexpr uint32_t T_B   = 2 * BM * 80;
    constexpr uint32_t STAGE = 2 * BM * 80 + 128 * 80;

    extern __shared__ __align__(16) char smem[];
    const int tid  = threadIdx.x;
    const int lane = tid & 31;
    const int wid  = tid >> 5;
    const int m0 = blockIdx.y * BM;
    const int n0 = blockIdx.x * 128;
    const int m_base = (wid % WM) * 32;
    const int n_base = (wid / WM) * (NI * 8);
    const uint32_t sbase = smem_u32(smem);

    const __half* gAh = Ahi + (size_t)m0 * Kpad;
    const __half* gAl = Alo + (size_t)m0 * Kpad;
    const __half* gB  = B   + (size_t)n0 * Kpad;

    float acc[2][NI][4];
#pragma unroll
    for (int mi = 0; mi < 2; mi++)
#pragma unroll
        for (int ni = 0; ni < NI; ni++)
#pragma unroll
            for (int v = 0; v < 4; v++) acc[mi][ni][v] = 0.f;

    const int stages = Kpad >> 5;

    auto load_stage = [&](int s, int buf) {
        const uint32_t sb = sbase + buf * STAGE;
        const int kofs = s << 5;
#pragma unroll
        for (int c = tid; c < BM * 4; c += 256) {
            const int rr = c >> 2, cc = c & 3;
            const uint32_t so = rr * 80 + cc * 16;
            const size_t go = (size_t)rr * Kpad + kofs + cc * 8;
            CP_ASYNC16(sb + so, gAh + go);
            CP_ASYNC16(sb + T_AL + so, gAl + go);
        }
#pragma unroll
        for (int c = tid; c < 512; c += 256) {
            const int rr = c >> 2, cc = c & 3;
            const uint32_t so = rr * 80 + cc * 16;
            const size_t go = (size_t)rr * Kpad + kofs + cc * 8;
            CP_ASYNC16(sb + T_B + so, gB + go);
        }
    };

    load_stage(0, 0);
    CP_COMMIT();

    for (int s = 0; s < stages; s++) {
        CP_WAIT0();
        __syncthreads();
        if (s + 1 < stages) { load_stage(s + 1, (s + 1) & 1); CP_COMMIT(); }
        const uint32_t sb = sbase + (s & 1) * STAGE;

#pragma unroll
        for (int step = 0; step < 2; step++) {
            const uint32_t kb = step * 32;
            uint32_t ah[2][4], al[2][4], b[NI][2];
            const uint32_t arow = (uint32_t)(m_base + (lane & 15)) * 80 + kb + (lane >> 4) * 16;
#pragma unroll
            for (int mi = 0; mi < 2; mi++) {
                const uint32_t ad = sb + arow + mi * (16 * 80);
                LDSM4(ah[mi][0], ah[mi][1], ah[mi][2], ah[mi][3], ad);
                LDSM4(al[mi][0], al[mi][1], al[mi][2], al[mi][3], ad + T_AL);
            }
            const uint32_t brow = (uint32_t)(n_base + (lane & 15)) * 80 + kb + (lane >> 4) * 16;
#pragma unroll
            for (int g = 0; g < NI / 2; g++) {
                uint32_t t0, t1, t2, t3;
                LDSM4(t0, t1, t2, t3, sb + T_B + brow + g * (16 * 80));
                b[2 * g][0] = t0; b[2 * g][1] = t2;
                b[2 * g + 1][0] = t1; b[2 * g + 1][1] = t3;
            }
            // pass 1: A_hi * B
#pragma unroll
            for (int mi = 0; mi < 2; mi++)
#pragma unroll
                for (int ni = 0; ni < NI; ni++)
                    MMA_F16(acc[mi][ni], ah[mi], b[ni][0], b[ni][1]);
            // pass 2: A_lo * B
#pragma unroll
            for (int mi = 0; mi < 2; mi++)
#pragma unroll
                for (int ni = 0; ni < NI; ni++)
                    MMA_F16(acc[mi][ni], al[mi], b[ni][0], b[ni][1]);
        }
    }

    // epilogue
    const int erow = lane >> 2;
    const int ecol = (lane & 3) * 2;
#pragma unroll
    for (int mi = 0; mi < 2; mi++) {
        const int mA = m0 + m_base + mi * 16 + erow;
        const int mB = mA + 8;
        const bool vA = mA < Mvalid, vB = mB < Mvalid;
        const float bA = vA ? bias[mA] : 0.f;
        const float bB = vB ? bias[mB] : 0.f;
#pragma unroll
        for (int ni = 0; ni < NI; ni++) {
            const int n = n0 + n_base + ni * 8 + ecol;
            float v00 = acc[mi][ni][0] + bA;
            float v01 = acc[mi][ni][1] + bA;
            float v10 = acc[mi][ni][2] + bB;
            float v11 = acc[mi][ni][3] + bB;
            if (RELU) {
                v00 = fmaxf(v00, 0.f); v01 = fmaxf(v01, 0.f);
                v10 = fmaxf(v10, 0.f); v11 = fmaxf(v11, 0.f);
            }
            if constexpr (HALF_OUT) {
                if (vA) {
                    Ch[(size_t)n * Dout + mA] = __float2half(v00);
                    Ch[(size_t)(n + 1) * Dout + mA] = __float2half(v01);
                }
                if (vB) {
                    Ch[(size_t)n * Dout + mB] = __float2half(v10);
                    Ch[(size_t)(n + 1) * Dout + mB] = __float2half(v11);
                }
            } else {
                if (vA) {
                    Cf[(size_t)n * Dout + mA] = v00;
                    Cf[(size_t)(n + 1) * Dout + mA] = v01;
                }
                if (vB) {
                    Cf[(size_t)n * Dout + mB] = v10;
                    Cf[(size_t)(n + 1) * Dout + mB] = v11;
                }
            }
        }
    }
}

// SMEM sizes per config
static constexpr int SMEM_A = 2 * (2 * 128 * 80 + 128 * 80);  // WM=4: 61440
static constexpr int SMEM_B = 2 * (2 * 64 * 80 + 128 * 80);   // WM=2: 40960

// ---------------------------------------------------------------------------
// Launch
// ---------------------------------------------------------------------------
extern "C" void kernel_launch(void* const* d_in, const int* in_sizes, int n_in,
                              void* d_out, int out_size) {
    const float* x    = (const float*)d_in[0];
    const float* h0   = (const float*)d_in[1];
    const float* W_ih = (const float*)d_in[2];
    const float* W_hh = (const float*)d_in[3];
    const float* b_ih = (const float*)d_in[4];
    const float* b_hh = (const float*)d_in[5];
    const float* w1   = (const float*)d_in[6];
    const float* b1   = (const float*)d_in[7];
    const float* w2   = (const float*)d_in[8];
    const float* b2   = (const float*)d_in[9];
    const float* w3   = (const float*)d_in[10];
    const float* b3   = (const float*)d_in[11];
    const float* w4   = (const float*)d_in[12];
    const float* b4   = (const float*)d_in[13];
    float* out = (float*)d_out;

    float *p_xw;
    __half *p_hs, *hsT, *a1, *a2, *a3;
    __half *w1h, *w1l, *w2h, *w2l, *w3h, *w3l, *w4h, *w4l;
    cudaGetSymbolAddress((void**)&p_xw, g_xw);
    cudaGetSymbolAddress((void**)&p_hs, g_hs_h);
    cudaGetSymbolAddress((void**)&hsT, g_hsT);
    cudaGetSymbolAddress((void**)&a1, g_a1);
    cudaGetSymbolAddress((void**)&a2, g_a2);
    cudaGetSymbolAddress((void**)&a3, g_a3);
    cudaGetSymbolAddress((void**)&w1h, g_w1_hi);
    cudaGetSymbolAddress((void**)&w1l, g_w1_lo);
    cudaGetSymbolAddress((void**)&w2h, g_w2_hi);
    cudaGetSymbolAddress((void**)&w2l, g_w2_lo);
    cudaGetSymbolAddress((void**)&w3h, g_w3_hi);
    cudaGetSymbolAddress((void**)&w3l, g_w3_lo);
    cudaGetSymbolAddress((void**)&w4h, g_w4_hi);
    cudaGetSymbolAddress((void**)&w4l, g_w4_lo);

    cudaFuncSetAttribute(mma_gemm_kernel<4, 8, true, true>,
                         cudaFuncAttributeMaxDynamicSharedMemorySize, SMEM_A);
    cudaFuncSetAttribute(mma_gemm_kernel<2, 4, true, true>,
                         cudaFuncAttributeMaxDynamicSharedMemorySize, SMEM_B);
    cudaFuncSetAttribute(mma_gemm_kernel<4, 8, false, false>,
                         cudaFuncAttributeMaxDynamicSharedMemorySize, SMEM_A);

    const size_t out_elems = (size_t)BATCH * SEQ;
    const int write_hidden = ((size_t)out_size >= out_elems + BATCH) ? 1 : 0;
    float* hid_out = out + out_elems;

    // Weight conversion: single launch
    weight_split_kernel<<<SPLIT_BLOCKS, 256>>>(w1, w2, w3, w4,
                                               w1h, w1l, w2h, w2l,
                                               w3h, w3l, w4h, w4l);

    // Input projection -> g_xw [t][b]
    {
        dim3 grid(BATCH / 32, (SEQ + 31) / 32);
        xw_kernel<<<grid, 256>>>(x, W_ih, b_ih, b_hh, p_xw);
    }
    // RNN scan -> fp16 hs [t][b], hidden tail fp32
    rnn_kernel<<<BATCH / 128, 128>>>(p_xw, h0, W_hh, p_hs, hid_out, write_hidden);

    // Transpose -> hsT [b][KP_T]
    {
        dim3 grid(BATCH / 64, KP_T / 64);
        transpose_kernel<<<grid, 256>>>(p_hs, hsT);
    }

    // L1: a1[b][D1] = relu(w1 . hs + b1)
    {
        dim3 grid(BATCH / 128, D1 / 128);
        mma_gemm_kernel<4, 8, true, true><<<grid, 256, SMEM_A>>>(
            w1h, w1l, hsT, b1, a1, nullptr, KP_T, D1, D1);
    }
    // L2: a2[b][D2] = relu(w2 . a1 + b2)
    {
        dim3 grid(BATCH / 128, D2 / 128);
        mma_gemm_kernel<4, 8, true, true><<<grid, 256, SMEM_A>>>(
            w2h, w2l, a1, b2, a2, nullptr, D1, D2, D2);
    }
    // L3: a3[b][D3] = relu(w3 . a2 + b3)   (BM=64 config -> 128 CTAs)
    {
        dim3 grid(BATCH / 128, D3 / 64);
        mma_gemm_kernel<2, 4, true, true><<<grid, 256, SMEM_B>>>(
            w3h, w3l, a2, b3, a3, nullptr, D2, D3, D3);
    }
    // L4: out[b][t] = w4 . a3 + b4  (fp32 out, m = t, guard m < SEQ)
    {
        dim3 grid(BATCH / 128, M4P / 128);
        mma_gemm_kernel<4, 8, false, false><<<grid, 256, SMEM_A>>>(
            w4h, w4l, a3, b4, nullptr, out, D3, SEQ, SEQ);
    }
}